// round 2
// baseline (speedup 1.0000x reference)
#include <cuda_runtime.h>
#include <cuda_bf16.h>

// Problem constants (fixed by the dataset)
#define HID   128
#define NRAD  16
#define MAX_NODES 50000

// Scratch: scatter-add accumulator x[n_nodes][128]
__device__ float g_x[MAX_NODES * HID];

// ---------------------------------------------------------------------------
// Kernel 0: zero the accumulator
// ---------------------------------------------------------------------------
__global__ void zero_x_kernel(int n_nodes) {
    int n4 = n_nodes * HID / 4;
    float4* p = reinterpret_cast<float4*>(g_x);
    for (int i = blockIdx.x * blockDim.x + threadIdx.x; i < n4; i += gridDim.x * blockDim.x)
        p[i] = make_float4(0.f, 0.f, 0.f, 0.f);
}

// ---------------------------------------------------------------------------
// Kernel 1: fused edge pipeline
//   W   = silu(rb @ rW1 + rb1) @ rW2 + rb2          [per edge, 128]
//   msg = h[src] * W
//   atomicAdd into g_x[dst]
// Persistent blocks; rW1/rW2 resident in smem; 64-edge tiles.
// Block = 256 threads: j = tid & 127 (feature), half = tid >> 7 (edge subtile).
// ---------------------------------------------------------------------------
#define E_TILE 64

// smem float offsets
#define EO_RW2 0                    // 128*128 = 16384
#define EO_RW1 16384                // 16*128  = 2048
#define EO_HID 18432                // 64*128  = 8192
#define EO_RB  26624                // 64*16   = 1024
#define EO_IDX 27648                // 128 ints (src 64 | dst 64)
#define EDGE_SMEM_FLOATS (27648 + 128)
#define EDGE_SMEM_BYTES  (EDGE_SMEM_FLOATS * 4)

__global__ __launch_bounds__(256, 2)
void edge_kernel(const float* __restrict__ h,
                 const float* __restrict__ radial,
                 const int*   __restrict__ ei,
                 const float* __restrict__ rW1, const float* __restrict__ rb1,
                 const float* __restrict__ rW2, const float* __restrict__ rb2,
                 int n_edges)
{
    extern __shared__ float smem[];
    float* s_rW2 = smem + EO_RW2;   // [k][j]
    float* s_rW1 = smem + EO_RW1;   // [k][j]
    float* s_hid = smem + EO_HID;   // [e][k]
    float* s_rb  = smem + EO_RB;    // [e][k]
    int*   s_src = reinterpret_cast<int*>(smem + EO_IDX);
    int*   s_dst = s_src + E_TILE;

    const int tid  = threadIdx.x;
    const int j    = tid & (HID - 1);
    const int half = tid >> 7;

    // Resident weights
    for (int i = tid; i < HID * HID; i += 256) s_rW2[i] = rW2[i];
    for (int i = tid; i < NRAD * HID; i += 256) s_rW1[i] = rW1[i];
    __syncthreads();

    float w1c[NRAD];
#pragma unroll
    for (int k = 0; k < NRAD; ++k) w1c[k] = s_rW1[k * HID + j];
    const float rb1j = rb1[j];
    const float rb2j = rb2[j];

    const int n_tiles = (n_edges + E_TILE - 1) / E_TILE;

    for (int t = blockIdx.x; t < n_tiles; t += gridDim.x) {
        const int e0 = t * E_TILE;
        __syncthreads();  // protect smem reuse across tiles

        // load radial tile (contiguous 64*16 floats)
        for (int i = tid; i < E_TILE * NRAD; i += 256) {
            int e = e0 + (i >> 4);
            s_rb[i] = (e < n_edges) ? radial[(size_t)e0 * NRAD + i] : 0.f;
        }
        if (tid < E_TILE) {
            int e = e0 + tid;
            s_src[tid] = (e < n_edges) ? ei[e] : 0;
            s_dst[tid] = (e < n_edges) ? ei[n_edges + e] : 0;
        }
        __syncthreads();

        // Phase 1: hidden = silu(rb @ rW1 + rb1)
        const int ebase = half * 32;
        for (int e = ebase; e < ebase + 32; ++e) {
            float a = rb1j;
#pragma unroll
            for (int k = 0; k < NRAD; ++k)
                a = fmaf(s_rb[e * NRAD + k], w1c[k], a);
            float sg = 1.f / (1.f + __expf(-a));
            s_hid[e * HID + j] = a * sg;
        }
        __syncthreads();

        // Phase 2: W = hidden @ rW2 + rb2 ; gather/scatter
        for (int g = 0; g < 32; g += 8) {
            float acc[8];
#pragma unroll
            for (int r = 0; r < 8; ++r) acc[r] = rb2j;
            const float* hidb = s_hid + (ebase + g) * HID;
#pragma unroll 4
            for (int k = 0; k < HID; ++k) {
                float w = s_rW2[k * HID + j];
#pragma unroll
                for (int r = 0; r < 8; ++r)
                    acc[r] = fmaf(hidb[r * HID + k], w, acc[r]);
            }
#pragma unroll
            for (int r = 0; r < 8; ++r) {
                int e  = ebase + g + r;
                int ge = e0 + e;
                if (ge < n_edges) {
                    int   sr = s_src[e];
                    float hv = __ldg(&h[(size_t)sr * HID + j]);
                    atomicAdd(&g_x[(size_t)s_dst[e] * HID + j], hv * acc[r]);
                }
            }
        }
    }
}

// ---------------------------------------------------------------------------
// Kernel 2: node-side dense stack
//   x = silu(x@dW0+db0); x = silu(x@dW1+db1); x = silu(x@dW2+db2); out = x@oW+ob
// All three 128x128 weights resident in smem (192KB). 32-node tiles.
// ---------------------------------------------------------------------------
#define N_TILE 32
#define NO_DW  0                    // 3*16384 = 49152
#define NO_X   49152                // 32*128  = 4096
#define NO_OW  53248                // 128
#define NODE_SMEM_FLOATS (53248 + 128)
#define NODE_SMEM_BYTES  (NODE_SMEM_FLOATS * 4)

__global__ __launch_bounds__(256, 1)
void node_kernel(const float* __restrict__ dW0, const float* __restrict__ db0,
                 const float* __restrict__ dW1, const float* __restrict__ db1,
                 const float* __restrict__ dW2, const float* __restrict__ db2,
                 const float* __restrict__ oW,  const float* __restrict__ ob,
                 float* __restrict__ out, int n_nodes)
{
    extern __shared__ float smem[];
    float* s_dW = smem + NO_DW;   // 3 layers of [k][j]
    float* s_x  = smem + NO_X;    // [n][k]
    float* s_oW = smem + NO_OW;

    const int tid  = threadIdx.x;
    const int j    = tid & (HID - 1);
    const int half = tid >> 7;
    const int lane = tid & 31;
    const int warp = tid >> 5;

    for (int i = tid; i < HID * HID; i += 256) {
        s_dW[i]                 = dW0[i];
        s_dW[HID * HID + i]     = dW1[i];
        s_dW[2 * HID * HID + i] = dW2[i];
    }
    if (tid < HID) s_oW[tid] = oW[tid];
    float dbj[3] = { db0[j], db1[j], db2[j] };
    const float obv = ob[0];
    __syncthreads();

    const int n_tiles = (n_nodes + N_TILE - 1) / N_TILE;

    for (int t = blockIdx.x; t < n_tiles; t += gridDim.x) {
        const int n0 = t * N_TILE;
        __syncthreads();
        for (int i = tid; i < N_TILE * HID; i += 256) {
            int n = n0 + (i >> 7);
            s_x[i] = (n < n_nodes) ? g_x[(size_t)n0 * HID + i] : 0.f;
        }
        __syncthreads();

        const int nbase = half * 16;
#pragma unroll 1
        for (int l = 0; l < 3; ++l) {
            const float* W = s_dW + l * HID * HID;
            float acc[16];
#pragma unroll
            for (int r = 0; r < 16; ++r) acc[r] = dbj[l];
            const float* xb = s_x + nbase * HID;
#pragma unroll 2
            for (int k = 0; k < HID; ++k) {
                float w = W[k * HID + j];
#pragma unroll
                for (int r = 0; r < 16; ++r)
                    acc[r] = fmaf(xb[r * HID + k], w, acc[r]);
            }
            __syncthreads();
#pragma unroll
            for (int r = 0; r < 16; ++r) {
                float a  = acc[r];
                float sg = 1.f / (1.f + __expf(-a));
                s_x[(nbase + r) * HID + j] = a * sg;
            }
            __syncthreads();
        }

        // output head: 8 warps x 4 nodes, warp shuffle reduce over 128 feats
#pragma unroll
        for (int nn = 0; nn < 4; ++nn) {
            int n = warp * 4 + nn;
            const float* xr = s_x + n * HID;
            float p = xr[lane]      * s_oW[lane]
                    + xr[lane + 32] * s_oW[lane + 32]
                    + xr[lane + 64] * s_oW[lane + 64]
                    + xr[lane + 96] * s_oW[lane + 96];
#pragma unroll
            for (int off = 16; off > 0; off >>= 1)
                p += __shfl_down_sync(0xffffffffu, p, off);
            if (lane == 0 && (n0 + n) < n_nodes)
                out[n0 + n] = p + obv;
        }
    }
}

// ---------------------------------------------------------------------------
extern "C" void kernel_launch(void* const* d_in, const int* in_sizes, int n_in,
                              void* d_out, int out_size)
{
    const float* h      = (const float*)d_in[0];
    const float* radial = (const float*)d_in[1];
    const int*   ei     = (const int*)  d_in[2];
    const float* rW1 = (const float*)d_in[3];
    const float* rb1 = (const float*)d_in[4];
    const float* rW2 = (const float*)d_in[5];
    const float* rb2 = (const float*)d_in[6];
    const float* dW0 = (const float*)d_in[7];
    const float* db0 = (const float*)d_in[8];
    const float* dW1 = (const float*)d_in[9];
    const float* db1 = (const float*)d_in[10];
    const float* dW2 = (const float*)d_in[11];
    const float* db2 = (const float*)d_in[12];
    const float* oW  = (const float*)d_in[13];
    const float* ob  = (const float*)d_in[14];
    float* out = (float*)d_out;

    const int n_nodes = in_sizes[0] / HID;
    const int n_edges = in_sizes[1] / NRAD;

    // Idempotent, not a stream op — legal during graph capture; no static guard.
    cudaFuncSetAttribute(edge_kernel, cudaFuncAttributeMaxDynamicSharedMemorySize, EDGE_SMEM_BYTES);
    cudaFuncSetAttribute(node_kernel, cudaFuncAttributeMaxDynamicSharedMemorySize, NODE_SMEM_BYTES);

    zero_x_kernel<<<512, 256>>>(n_nodes);
    edge_kernel<<<304, 256, EDGE_SMEM_BYTES>>>(h, radial, ei, rW1, rb1, rW2, rb2, n_edges);
    node_kernel<<<152, 256, NODE_SMEM_BYTES>>>(dW0, db0, dW1, db1, dW2, db2, oW, ob, out, n_nodes);
}